// round 2
// baseline (speedup 1.0000x reference)
#include <cuda_runtime.h>
#include <math.h>

// Problem constants (fixed shapes from setup_inputs)
#define B_  4
#define NH  8
#define HD  32
#define NS  2304     // 48*48
#define CC  256      // channels = NH*HD
#define TN  64       // q rows per block
#define TM  64       // k/v cols per tile

// scratch for pre-projection output, layout (b, head*HD + c, n) = (4,256,2304)
__device__ float g_pre[B_ * CC * NS];

// ---------------------------------------------------------------------------
// Fused attention: l2norm(q),l2norm(k) folded as scalars; exp(relu(.)) softmax
// (stable without max since relu>=0 and |q.k|<=1); O accumulated in registers.
// ---------------------------------------------------------------------------
__global__ __launch_bounds__(256, 2) void attn_kernel(
    const float* __restrict__ qkv, const float* __restrict__ temp)
{
    __shared__ float Qs[TN][HD + 1];
    __shared__ float Ks[TM][HD + 1];
    __shared__ float Vs[TM][HD + 2];          // pitch 34 -> aligned float2 reads
    __shared__ float Ps[TN][TM + 1];          // 64x65; reused as Os (pitch 34)
    __shared__ float qinv[TN], kinv[TM], rowsum[TN];

    const int tid = threadIdx.x;
    const int bh  = blockIdx.y;
    const int b   = bh >> 3, hh = bh & 7;
    const int n0  = blockIdx.x * TN;

    const float th = temp[hh];

    const size_t baseQ = ((size_t)(b * 3 * CC) + hh * HD) * NS;
    const size_t baseK = baseQ + (size_t)CC * NS;
    const size_t baseV = baseK + (size_t)CC * NS;

    // ---- load Q tile (coalesced along n), compute 1/||q|| -----------------
    #pragma unroll
    for (int idx = tid; idx < TN * HD; idx += 256) {
        int c = idx / TN, i = idx % TN;
        Qs[i][c] = qkv[baseQ + (size_t)c * NS + n0 + i];
    }
    __syncthreads();
    if (tid < TN) {
        float s = 0.f;
        #pragma unroll
        for (int c = 0; c < HD; c++) { float v = Qs[tid][c]; s += v * v; }
        qinv[tid] = 1.0f / fmaxf(sqrtf(s), 1e-12f);
    }

    // phase-1 mapping: thread (ty,tx) -> S rows ty*4.., cols tx*4..
    const int tx = tid & 15, ty = tid >> 4;
    const int i0 = ty * 4,  j0 = tx * 4;
    // phase-2 mapping: rows ty*4.., output dims c0 = tx*2
    const int i0b = ty * 4, c0 = tx * 2;

    float oacc[4][2] = {};
    float racc[4]    = {0.f, 0.f, 0.f, 0.f};

    for (int m0 = 0; m0 < NS; m0 += TM) {
        __syncthreads();   // previous iter done with Ks/Vs/Ps (and Q-norm done)

        // ---- load K,V tiles; compute 1/||k|| ------------------------------
        #pragma unroll
        for (int idx = tid; idx < TM * HD; idx += 256) {
            int c = idx / TM, j = idx % TM;
            Ks[j][c] = qkv[baseK + (size_t)c * NS + m0 + j];
            Vs[j][c] = qkv[baseV + (size_t)c * NS + m0 + j];
        }
        __syncthreads();
        if (tid < TM) {
            float s = 0.f;
            #pragma unroll
            for (int c = 0; c < HD; c++) { float v = Ks[tid][c]; s += v * v; }
            kinv[tid] = 1.0f / fmaxf(sqrtf(s), 1e-12f);
        }
        __syncthreads();

        // ---- S = Q K^T, 4x4 micro-tile per thread -------------------------
        float s[4][4] = {};
        #pragma unroll
        for (int c = 0; c < HD; c++) {
            float a[4], bb[4];
            #pragma unroll
            for (int r = 0; r < 4; r++) a[r]  = Qs[i0 + r][c];
            #pragma unroll
            for (int t = 0; t < 4; t++) bb[t] = Ks[j0 + t][c];
            #pragma unroll
            for (int r = 0; r < 4; r++)
                #pragma unroll
                for (int t = 0; t < 4; t++)
                    s[r][t] += a[r] * bb[t];
        }

        // ---- P = exp(relu(temp * s / (|q||k|))); accumulate row sums ------
        #pragma unroll
        for (int r = 0; r < 4; r++) {
            const float qi = qinv[i0 + r] * th;
            #pragma unroll
            for (int t = 0; t < 4; t++) {
                float x = s[r][t] * qi * kinv[j0 + t];
                float p = __expf(fmaxf(x, 0.0f));
                racc[r] += p;
                Ps[i0 + r][j0 + t] = p;
            }
        }
        __syncthreads();

        // ---- O += P * V (rows i0b..+3, dims c0,c0+1) ----------------------
        #pragma unroll
        for (int j = 0; j < TM; j++) {
            float2 v2 = *(const float2*)&Vs[j][c0];
            #pragma unroll
            for (int r = 0; r < 4; r++) {
                float p = Ps[i0b + r][j];
                oacc[r][0] += p * v2.x;
                oacc[r][1] += p * v2.y;
            }
        }
    }

    // ---- reduce row sums across tx (16 lanes within warp half) ------------
    #pragma unroll
    for (int r = 0; r < 4; r++) {
        float v = racc[r];
        v += __shfl_xor_sync(0xffffffffu, v, 1);
        v += __shfl_xor_sync(0xffffffffu, v, 2);
        v += __shfl_xor_sync(0xffffffffu, v, 4);
        v += __shfl_xor_sync(0xffffffffu, v, 8);
        if (tx == 0) rowsum[i0 + r] = v;
    }
    __syncthreads();   // rowsum visible; everyone done reading Ps

    // ---- scale, stage to smem (reuse Ps as Os, pitch HD+2) ----------------
    float* Os = &Ps[0][0];
    #pragma unroll
    for (int r = 0; r < 4; r++) {
        float sc = 1.0f / rowsum[i0b + r];
        Os[(i0b + r) * (HD + 2) + c0]     = oacc[r][0] * sc;
        Os[(i0b + r) * (HD + 2) + c0 + 1] = oacc[r][1] * sc;
    }
    __syncthreads();

    // ---- coalesced write to g_pre (b, hh*HD+c, n) --------------------------
    const size_t baseO = ((size_t)(b * CC) + hh * HD) * NS;
    #pragma unroll
    for (int idx = tid; idx < TN * HD; idx += 256) {
        int c = idx / TN, i = idx % TN;
        g_pre[baseO + (size_t)c * NS + n0 + i] = Os[i * (HD + 2) + c];
    }
}

// ---------------------------------------------------------------------------
// 1x1 conv as GEMM: out[b,o,n] = sum_ch W[o,ch]*pre[b,ch,n] + bias[o]
// ---------------------------------------------------------------------------
#define PO 64
#define PN 64
#define PK 16

__global__ __launch_bounds__(256) void proj_kernel(
    const float* __restrict__ W, const float* __restrict__ bias,
    float* __restrict__ out)
{
    __shared__ float Ws[PO][PK + 1];
    __shared__ float Xs[PK][PN + 1];

    const int tid = threadIdx.x;
    const int tx = tid & 15, ty = tid >> 4;
    const int n0 = blockIdx.x * PN;
    const int o0 = blockIdx.y * PO;
    const int b  = blockIdx.z;

    const float* preb = g_pre + (size_t)b * CC * NS;
    float acc[4][4] = {};

    for (int k0 = 0; k0 < CC; k0 += PK) {
        __syncthreads();
        #pragma unroll
        for (int idx = tid; idx < PO * PK; idx += 256) {
            int o = idx >> 4, k = idx & 15;
            Ws[o][k] = W[(size_t)(o0 + o) * CC + k0 + k];
        }
        #pragma unroll
        for (int idx = tid; idx < PK * PN; idx += 256) {
            int k = idx >> 6, n = idx & 63;
            Xs[k][n] = preb[(size_t)(k0 + k) * NS + n0 + n];
        }
        __syncthreads();
        #pragma unroll
        for (int kk = 0; kk < PK; kk++) {
            float a[4], bb[4];
            #pragma unroll
            for (int r = 0; r < 4; r++) a[r]  = Ws[ty * 4 + r][kk];
            #pragma unroll
            for (int t = 0; t < 4; t++) bb[t] = Xs[kk][tx + 16 * t];
            #pragma unroll
            for (int r = 0; r < 4; r++)
                #pragma unroll
                for (int t = 0; t < 4; t++)
                    acc[r][t] += a[r] * bb[t];
        }
    }

    #pragma unroll
    for (int r = 0; r < 4; r++) {
        float bv = bias[o0 + ty * 4 + r];
        #pragma unroll
        for (int t = 0; t < 4; t++) {
            out[((size_t)b * CC + o0 + ty * 4 + r) * NS + n0 + tx + 16 * t]
                = acc[r][t] + bv;
        }
    }
}

extern "C" void kernel_launch(void* const* d_in, const int* in_sizes, int n_in,
                              void* d_out, int out_size) {
    const float* qkv  = (const float*)d_in[0];
    const float* temp = (const float*)d_in[1];
    const float* W    = (const float*)d_in[2];
    const float* bias = (const float*)d_in[3];
    float* out = (float*)d_out;

    attn_kernel<<<dim3(NS / TN, B_ * NH), 256>>>(qkv, temp);
    proj_kernel<<<dim3(NS / PN, CC / PO, B_), 256>>>(W, bias, out);
}

// round 5
// speedup vs baseline: 2.6435x; 2.6435x over previous
#include <cuda_runtime.h>
#include <cstdint>
#include <math.h>

// Problem constants
#define B_   4
#define NH   8
#define HD   32
#define NS   2304     // 48*48
#define CC   256
#define TQ   128      // q rows per CTA (4 warps x 32)
#define TK   64       // kv rows per tile
#define NT   (NS / TK) // 36

// dynamic smem layout (float offsets)
#define PW_OFF  0        // per-warp P: 4 x [32][68]  (warp base = w*2176)
#define QP_OFF  0        // Q staging [32][136], overlaps PW (dead after frag extract)
#define KT_OFF  8704     // K~ [64 rows j][36]  (k-interleaved cols)
#define VP_OFF  11008    // V~ [32 rows c][68]  (k-interleaved cols)
#define QS_OFF  13184    // 128 floats: temp/||q||
#define KI_OFF  13312    // 64 floats: 1/||k||
#define SM_FLOATS 13376
#define SM_BYTES  (SM_FLOATS * 4)

__device__ float g_pre[B_ * CC * NS];

// round-to-nearest tf32 (keep as float bits)
__device__ __forceinline__ float tf32r(float x) {
    uint32_t u;
    asm("cvt.rna.tf32.f32 %0, %1;" : "=r"(u) : "f"(x));
    return __uint_as_float(u);
}
__device__ __forceinline__ uint32_t fb(float x) { return __float_as_uint(x); }

__device__ __forceinline__ void mma_tf32(float& c0, float& c1, float& c2, float& c3,
                                         uint32_t a0, uint32_t a1, uint32_t a2, uint32_t a3,
                                         uint32_t b0, uint32_t b1) {
    asm volatile("mma.sync.aligned.m16n8k8.row.col.f32.tf32.tf32.f32 "
                 "{%0,%1,%2,%3}, {%4,%5,%6,%7}, {%8,%9}, {%0,%1,%2,%3};"
                 : "+f"(c0), "+f"(c1), "+f"(c2), "+f"(c3)
                 : "r"(a0), "r"(a1), "r"(a2), "r"(a3), "r"(b0), "r"(b1));
}

// ---------------------------------------------------------------------------
// Fused attention, tf32 mma.sync, m32 per warp
// ---------------------------------------------------------------------------
__global__ __launch_bounds__(128, 2) void attn_kernel(
    const float* __restrict__ qkv, const float* __restrict__ temp)
{
    extern __shared__ float sm[];

    const int tid  = threadIdx.x;
    const int lane = tid & 31;
    const int w    = tid >> 5;       // warp 0..3 -> q rows w*32..w*32+31
    const int q4   = lane & 3;       // tig
    const int g    = lane >> 2;      // groupID

    const int bh = blockIdx.y;
    const int b  = bh >> 3, hh = bh & 7;
    const int n0 = blockIdx.x * TQ;
    const float th = temp[hh];

    const size_t baseQ = ((size_t)(b * 3 * CC) + hh * HD) * NS;
    const size_t baseK = baseQ + (size_t)CC * NS;
    const size_t baseV = baseK + (size_t)CC * NS;

    // ---- Q tile: thread owns q row n=tid; coalesced per c ----
    {
        float sq = 0.f;
        #pragma unroll
        for (int c = 0; c < HD; c++) {
            float v = qkv[baseQ + (size_t)c * NS + n0 + tid];
            sq += v * v;
            sm[QP_OFF + c * 136 + tid] = tf32r(v);
        }
        sm[QS_OFF + tid] = th / fmaxf(sqrtf(sq), 1e-12f);
    }
    __syncthreads();

    // ---- extract persistent Q A-frags: aq[kc][mt][0..3] ----
    uint32_t aq[4][2][4];
    #pragma unroll
    for (int kc = 0; kc < 4; kc++)
        #pragma unroll
        for (int mt = 0; mt < 2; mt++) {
            int R = w * 32 + mt * 16 + g;
            aq[kc][mt][0] = fb(sm[QP_OFF + (8 * kc + q4) * 136 + R]);
            aq[kc][mt][1] = fb(sm[QP_OFF + (8 * kc + q4) * 136 + R + 8]);
            aq[kc][mt][2] = fb(sm[QP_OFF + (8 * kc + q4 + 4) * 136 + R]);
            aq[kc][mt][3] = fb(sm[QP_OFF + (8 * kc + q4 + 4) * 136 + R + 8]);
        }
    float qsv[2][2];
    #pragma unroll
    for (int mt = 0; mt < 2; mt++) {
        qsv[mt][0] = sm[QS_OFF + w * 32 + mt * 16 + g];
        qsv[mt][1] = sm[QS_OFF + w * 32 + mt * 16 + g + 8];
    }

    float o[2][4][4] = {};
    float racc[2][2] = {};
    const int pwbase = PW_OFF + w * 2176;

    #pragma unroll 1
    for (int t = 0; t < NT; t++) {
        const int m0 = t * TK;

        // ---- load K (warps 0-1) / V (warps 2-3) ----
        if (tid < 64) {
            const int j = tid;
            float kbuf[HD];
            float sk = 0.f;
            #pragma unroll
            for (int c = 0; c < HD; c++) {
                float v = qkv[baseK + (size_t)c * NS + m0 + j];
                sk += v * v;
                kbuf[c] = tf32r(v);
            }
            sm[KI_OFF + j] = 1.0f / fmaxf(sqrtf(sk), 1e-12f);
            // store k-interleaved: pos p=8q+4u+s <- c=(4u+s)*4+q
            #pragma unroll
            for (int q = 0; q < 4; q++)
                #pragma unroll
                for (int u = 0; u < 2; u++) {
                    float4 f = make_float4(kbuf[(4 * u + 0) * 4 + q], kbuf[(4 * u + 1) * 4 + q],
                                           kbuf[(4 * u + 2) * 4 + q], kbuf[(4 * u + 3) * 4 + q]);
                    *(float4*)&sm[KT_OFF + j * 36 + 8 * q + 4 * u] = f;
                }
        } else {
            const int j = tid - 64;
            const int rj = (j & 3) * 16 + (j >> 2);   // rho(j)
            #pragma unroll
            for (int c = 0; c < HD; c++) {
                float v = qkv[baseV + (size_t)c * NS + m0 + j];
                sm[VP_OFF + c * 68 + rj] = tf32r(v);
            }
        }
        __syncthreads();

        // ---- MMA1: S(32x64) = Q(32x32) K^T ----
        float s[2][8][4] = {};
        #pragma unroll
        for (int nt = 0; nt < 8; nt++) {
            const float4 bq0 = *(const float4*)&sm[KT_OFF + (nt * 8 + g) * 36 + 8 * q4];
            const float4 bq1 = *(const float4*)&sm[KT_OFF + (nt * 8 + g) * 36 + 8 * q4 + 4];
            #pragma unroll
            for (int mt = 0; mt < 2; mt++) {
                mma_tf32(s[mt][nt][0], s[mt][nt][1], s[mt][nt][2], s[mt][nt][3],
                         aq[0][mt][0], aq[0][mt][1], aq[0][mt][2], aq[0][mt][3], fb(bq0.x), fb(bq0.y));
                mma_tf32(s[mt][nt][0], s[mt][nt][1], s[mt][nt][2], s[mt][nt][3],
                         aq[1][mt][0], aq[1][mt][1], aq[1][mt][2], aq[1][mt][3], fb(bq0.z), fb(bq0.w));
                mma_tf32(s[mt][nt][0], s[mt][nt][1], s[mt][nt][2], s[mt][nt][3],
                         aq[2][mt][0], aq[2][mt][1], aq[2][mt][2], aq[2][mt][3], fb(bq1.x), fb(bq1.y));
                mma_tf32(s[mt][nt][0], s[mt][nt][1], s[mt][nt][2], s[mt][nt][3],
                         aq[3][mt][0], aq[3][mt][1], aq[3][mt][2], aq[3][mt][3], fb(bq1.z), fb(bq1.w));
            }
        }

        // ---- P = exp(relu(qs*kinv*S)); store to per-warp P buffer ----
        #pragma unroll
        for (int nt = 0; nt < 8; nt++) {
            const float2 kv = *(const float2*)&sm[KI_OFF + nt * 8 + 2 * q4];
            const int rho = 32 * (q4 & 1) + 2 * nt + (q4 >> 1);
            #pragma unroll
            for (int mt = 0; mt < 2; mt++) {
                float p00 = __expf(fmaxf(s[mt][nt][0] * qsv[mt][0] * kv.x, 0.f));
                float p01 = __expf(fmaxf(s[mt][nt][1] * qsv[mt][0] * kv.y, 0.f));
                float p10 = __expf(fmaxf(s[mt][nt][2] * qsv[mt][1] * kv.x, 0.f));
                float p11 = __expf(fmaxf(s[mt][nt][3] * qsv[mt][1] * kv.y, 0.f));
                racc[mt][0] += p00 + p01;
                racc[mt][1] += p10 + p11;
                const int r0 = pwbase + (mt * 16 + g) * 68;
                const int r1 = r0 + 8 * 68;
                sm[r0 + rho]      = tf32r(p00);
                sm[r0 + rho + 16] = tf32r(p01);
                sm[r1 + rho]      = tf32r(p10);
                sm[r1 + rho + 16] = tf32r(p11);
            }
        }
        __syncwarp();

        // ---- reload P as A-frags (contiguous 16 floats per row) ----
        float pa[2][16], pb[2][16];
        #pragma unroll
        for (int mt = 0; mt < 2; mt++) {
            const int r0 = pwbase + (mt * 16 + g) * 68 + 16 * q4;
            const int r1 = r0 + 8 * 68;
            #pragma unroll
            for (int u = 0; u < 4; u++) {
                *(float4*)&pa[mt][4 * u] = *(const float4*)&sm[r0 + 4 * u];
                *(float4*)&pb[mt][4 * u] = *(const float4*)&sm[r1 + 4 * u];
            }
        }

        // ---- MMA2: O(32x32) += P(32x64) V(64x32) ----
        #pragma unroll
        for (int nt2 = 0; nt2 < 4; nt2++) {
            float bv[16];
            const int vr = VP_OFF + (nt2 * 8 + g) * 68 + 16 * q4;
            #pragma unroll
            for (int u = 0; u < 4; u++)
                *(float4*)&bv[4 * u] = *(const float4*)&sm[vr + 4 * u];
            #pragma unroll
            for (int mt = 0; mt < 2; mt++)
                #pragma unroll
                for (int kc = 0; kc < 8; kc++)
                    mma_tf32(o[mt][nt2][0], o[mt][nt2][1], o[mt][nt2][2], o[mt][nt2][3],
                             fb(pa[mt][2 * kc]), fb(pb[mt][2 * kc]),
                             fb(pa[mt][2 * kc + 1]), fb(pb[mt][2 * kc + 1]),
                             fb(bv[2 * kc]), fb(bv[2 * kc + 1]));
        }
        __syncthreads();   // Kt/Vp/kinv and P consumed before next tile overwrites
    }

    // ---- rowsum reduce across the 4-lane q4 group ----
    #pragma unroll
    for (int mt = 0; mt < 2; mt++)
        #pragma unroll
        for (int hf = 0; hf < 2; hf++) {
            float v = racc[mt][hf];
            v += __shfl_xor_sync(0xffffffffu, v, 1);
            v += __shfl_xor_sync(0xffffffffu, v, 2);
            racc[mt][hf] = 1.0f / v;
        }

    // ---- write O to g_pre[b, hh*HD + c, n] ----
    const size_t baseO = ((size_t)(b * CC) + hh * HD) * NS;
    #pragma unroll
    for (int mt = 0; mt < 2; mt++) {
        const int row = n0 + w * 32 + mt * 16 + g;
        #pragma unroll
        for (int nt2 = 0; nt2 < 4; nt2++) {
            int c0 = nt2 * 8 + 2 * q4;
            g_pre[baseO + (size_t)c0 * NS + row]           = o[mt][nt2][0] * racc[mt][0];
            g_pre[baseO + (size_t)(c0 + 1) * NS + row]     = o[mt][nt2][1] * racc[mt][0];
            g_pre[baseO + (size_t)c0 * NS + row + 8]       = o[mt][nt2][2] * racc[mt][1];
            g_pre[baseO + (size_t)(c0 + 1) * NS + row + 8] = o[mt][nt2][3] * racc[mt][1];
        }
    }
}

// ---------------------------------------------------------------------------
// 1x1 conv as fp32 GEMM (unchanged, known good)
// ---------------------------------------------------------------------------
#define PO 64
#define PN 64
#define PK 16

__global__ __launch_bounds__(256) void proj_kernel(
    const float* __restrict__ W, const float* __restrict__ bias,
    float* __restrict__ out)
{
    __shared__ float Ws[PO][PK + 1];
    __shared__ float Xs[PK][PN + 1];

    const int tid = threadIdx.x;
    const int tx = tid & 15, ty = tid >> 4;
    const int n0 = blockIdx.x * PN;
    const int o0 = blockIdx.y * PO;
    const int b  = blockIdx.z;

    const float* preb = g_pre + (size_t)b * CC * NS;
    float acc[4][4] = {};

    for (int k0 = 0; k0 < CC; k0 += PK) {
        __syncthreads();
        #pragma unroll
        for (int idx = tid; idx < PO * PK; idx += 256) {
            int oo = idx >> 4, k = idx & 15;
            Ws[oo][k] = W[(size_t)(o0 + oo) * CC + k0 + k];
        }
        #pragma unroll
        for (int idx = tid; idx < PK * PN; idx += 256) {
            int k = idx >> 6, n = idx & 63;
            Xs[k][n] = preb[(size_t)(k0 + k) * NS + n0 + n];
        }
        __syncthreads();
        #pragma unroll
        for (int kk = 0; kk < PK; kk++) {
            float a[4], bb[4];
            #pragma unroll
            for (int r = 0; r < 4; r++) a[r]  = Ws[ty * 4 + r][kk];
            #pragma unroll
            for (int t2 = 0; t2 < 4; t2++) bb[t2] = Xs[kk][tx + 16 * t2];
            #pragma unroll
            for (int r = 0; r < 4; r++)
                #pragma unroll
                for (int t2 = 0; t2 < 4; t2++)
                    acc[r][t2] += a[r] * bb[t2];
        }
    }

    #pragma unroll
    for (int r = 0; r < 4; r++) {
        float bv = bias[o0 + ty * 4 + r];
        #pragma unroll
        for (int t2 = 0; t2 < 4; t2++) {
            out[((size_t)b * CC + o0 + ty * 4 + r) * NS + n0 + tx + 16 * t2]
                = acc[r][t2] + bv;
        }
    }
}

extern "C" void kernel_launch(void* const* d_in, const int* in_sizes, int n_in,
                              void* d_out, int out_size) {
    const float* qkv  = (const float*)d_in[0];
    const float* temp = (const float*)d_in[1];
    const float* W    = (const float*)d_in[2];
    const float* bias = (const float*)d_in[3];
    float* out = (float*)d_out;

    cudaFuncSetAttribute(attn_kernel, cudaFuncAttributeMaxDynamicSharedMemorySize, SM_BYTES);
    attn_kernel<<<dim3(NS / TQ, B_ * NH), 128, SM_BYTES>>>(qkv, temp);
    proj_kernel<<<dim3(NS / PN, CC / PO, B_), 256>>>(W, bias, out);
}